// round 13
// baseline (speedup 1.0000x reference)
#include <cuda_runtime.h>
#include <cstdint>

#define CTC_V  128
#define NEG2   (-1.0e30f)
#define KS     8                 // time steps per block (== halo depth)
#define UW     (32 - KS)         // useful lanes per warp (24)
#define NW     11
#define NTHR   (NW * 32)         // 352
#define TMAX   1024
#define BMAX   64
#define TP     (TMAX + KS)       // padded time extent

// Scratch: per-(b,t) log2-sum-exp and blank log2-prob (padded in t).
__device__ float g_blank[BMAX * TP];
__device__ float g_lse[BMAX * TP];

__device__ __forceinline__ float ex2(float x) {
    float y; asm("ex2.approx.ftz.f32 %0, %1;" : "=f"(y) : "f"(x)); return y;
}
__device__ __forceinline__ float lg2(float x) {
    float y; asm("lg2.approx.ftz.f32 %0, %1;" : "=f"(y) : "f"(x)); return y;
}
// Exact renorm: fold R's exponent into M; R -> [1,2). Zero/denorm R safe.
__device__ __forceinline__ void renorm(float& M, float& R) {
    unsigned u = __float_as_uint(R);
    unsigned eb = u >> 23;
    int e = (eb != 0u) ? (int)eb - 127 : 0;
    R = __uint_as_float(u - ((unsigned)e << 23));
    M += (float)e;
}
__device__ __forceinline__ void barpair(int id) {
    asm volatile("bar.sync %0, %1;" :: "r"(id), "r"(64) : "memory");
}

// ---------------------------------------------------------------------------
// Kernel 1: per-(t,b) log2-sum-exp of acts*log2e (2 rows per warp).
// Writes ONLY lse + blank (0.5 MB) — acts stay L2-resident for kernel 2.
// ---------------------------------------------------------------------------
__global__ void lse_k(const float* __restrict__ acts, int rows, int T, int B) {
    int gw   = (blockIdx.x * blockDim.x + threadIdx.x) >> 5;
    int lane = threadIdx.x & 31;
    int r0 = gw * 2;
    if (r0 >= rows) return;
    int r1 = r0 + 1;                       // rows = T*B is even
    const float L2E = 1.4426950408889634f;
    float4 va = reinterpret_cast<const float4*>(acts)[(size_t)r0 * 32 + lane];
    float4 vb = reinterpret_cast<const float4*>(acts)[(size_t)r1 * 32 + lane];
    float a0 = va.x * L2E, a1 = va.y * L2E, a2 = va.z * L2E, a3 = va.w * L2E;
    float b0 = vb.x * L2E, b1 = vb.y * L2E, b2 = vb.z * L2E, b3 = vb.w * L2E;
    float ma = fmaxf(fmaxf(a0, a1), fmaxf(a2, a3));
    float mb = fmaxf(fmaxf(b0, b1), fmaxf(b2, b3));
#pragma unroll
    for (int o = 16; o; o >>= 1) {
        ma = fmaxf(ma, __shfl_xor_sync(0xffffffffu, ma, o));
        mb = fmaxf(mb, __shfl_xor_sync(0xffffffffu, mb, o));
    }
    float sa = ex2(a0 - ma) + ex2(a1 - ma) + ex2(a2 - ma) + ex2(a3 - ma);
    float sb = ex2(b0 - mb) + ex2(b1 - mb) + ex2(b2 - mb) + ex2(b3 - mb);
#pragma unroll
    for (int o = 16; o; o >>= 1) {
        sa += __shfl_xor_sync(0xffffffffu, sa, o);
        sb += __shfl_xor_sync(0xffffffffu, sb, o);
    }
    float la = lg2(sa) + ma, lb = lg2(sb) + mb;
    if (lane == 0) {
        int t0 = r0 / B, bb0 = r0 - t0 * B;
        int t1 = r1 / B, bb1 = r1 - t1 * B;
        g_blank[bb0 * TP + t0] = a0 - la;
        g_lse  [bb0 * TP + t0] = la;
        g_blank[bb1 * TP + t1] = b0 - lb;
        g_lse  [bb1 * TP + t1] = lb;
    }
}

// ---------------------------------------------------------------------------
// Kernel 2: alpha recursion, streaming (M,R) logsumexp, common-max step.
// Register-resident state: useful lanes never reload; only halo lanes (8)
// reload and only boundary lanes (24-31) store each block. Pairwise named
// barriers (ids 1..NW-1) replace __syncthreads in the loop. Fused cost.
// ---------------------------------------------------------------------------
__global__ __launch_bounds__(NTHR, 1) void ctc_alpha_k(
    float* __restrict__ out, const float* __restrict__ acts,
    const int* __restrict__ labels, const int* __restrict__ act_lens,
    const int* __restrict__ label_lens, int T, int B, int L)
{
    __shared__ __align__(16) float4 shA[2][NW * UW];
    __shared__ float2 shF[NW * UW];

    const int V = CTC_V;
    const int b = blockIdx.x;
    const int P = L + 1;
    const int tid = threadIdx.x, lane = tid & 31, w = tid >> 5;
    const float L2E = 1.4426950408889634f;

    int Tlen = act_lens[b];
    if (Tlen > T) Tlen = T;
    if (Tlen < 1) Tlen = 1;

    const int p = w * UW + lane - KS;
    const bool in0 = ((unsigned)p < (unsigned)P);
    const bool in1 = ((unsigned)p < (unsigned)L);
    const int  lab   = in1 ? labels[b * L + p] : 0;
    const bool allow = in1 && (p >= 1) && (lab != labels[b * L + p - 1]);
    const bool useful = (lane >= KS) && in0;

    const float* __restrict__ pl = acts + (size_t)b * V + lab;   // raw acts
    const float* __restrict__ pb = g_blank + (size_t)b * TP;
    const float* __restrict__ ps = g_lse   + (size_t)b * TP;
    const size_t rstr = (size_t)B * V;

    // ---- t = 0 init (purely local: every lane, incl. halo) ----
    float M0 = NEG2, R0 = 1.0f, M1 = NEG2, R1 = 1.0f;
    if (p == 0) {
        M0 = __ldg(pb);
        if (in1) M1 = fmaf(__ldg(pl), L2E, -__ldg(ps));
    }

    // emits for block 0 (t = 1..KS); acts index clamped to valid range
    float eb[KS], el[KS];
#pragma unroll
    for (int j = 0; j < KS; ++j) {
        int t = 1 + j;
        int tc = t < Tlen ? t : Tlen - 1;
        eb[j] = __ldg(pb + t);
        float ls = __ldg(ps + t);
        el[j] = fmaf(__ldg(pl + (size_t)tc * rstr), L2E, -ls);
    }

    const int NB     = (Tlen - 1 + KS - 1) / KS;
    const int NBfull = NB > 0 ? NB - 1 : 0;

    for (int blk = 0; blk < NBfull; ++blk) {
        // halo lanes refresh from left neighbor's last stored boundary
        if (blk > 0 && lane < KS) {
            float4 v = (p >= 0) ? shA[blk & 1][p] : make_float4(NEG2, 1.f, NEG2, 1.f);
            M0 = v.x; R0 = v.y; M1 = v.z; R1 = v.w;
        }
        // prefetch next block's emits
        float nb_[KS], nl_[KS];
        {
            int tb = (blk + 1) * KS + 1;
#pragma unroll
            for (int j = 0; j < KS; ++j) {
                int t = tb + j;
                int tc = t < Tlen ? t : Tlen - 1;
                nb_[j] = __ldg(pb + t);
                float ls = __ldg(ps + t);
                nl_[j] = fmaf(__ldg(pl + (size_t)tc * rstr), L2E, -ls);
            }
        }

        // 8 common-max steps, unpredicated
#pragma unroll
        for (int j = 0; j < KS; ++j) {
            float zM = __shfl_up_sync(0xffffffffu, M1, 1);
            float zR = __shfl_up_sync(0xffffffffu, R1, 1);
            float mC = fmaxf(fmaxf(M0, M1), zM);
            float x0 = ex2(M0 - mC);
            float x1 = ex2(M1 - mC);
            float xz = ex2(zM - mC);
            float R0x0 = R0 * x0;
            float Rzxz = zR * xz;
            float Rzg  = allow ? Rzxz : 0.0f;
            R0 = R0x0 + Rzxz;
            R1 = fmaf(R1, x1, R0x0 + Rzg);
            M0 = mC + eb[j];
            M1 = mC + el[j];
        }
        renorm(M0, R0); renorm(M1, R1);

        // boundary lanes publish for the right neighbor's halo
        if (lane >= UW) shA[(blk + 1) & 1][p] = make_float4(M0, R0, M1, R1);

        // pairwise neighbor sync (ids 1..NW-1; id 0 reserved for syncthreads)
        if (w > 0)      barpair(w);
        if (w < NW - 1) barpair(w + 1);

#pragma unroll
        for (int j = 0; j < KS; ++j) { eb[j] = nb_[j]; el[j] = nl_[j]; }
    }

    // ---- tail block (predicated, per-state max) ----
    if (NB > 0) {
        int blk = NBfull;
        if (blk > 0 && lane < KS) {
            float4 v = (p >= 0) ? shA[blk & 1][p] : make_float4(NEG2, 1.f, NEG2, 1.f);
            M0 = v.x; R0 = v.y; M1 = v.z; R1 = v.w;
        }
#pragma unroll
        for (int j = 0; j < KS; ++j) {
            int t = blk * KS + 1 + j;
            float zM = __shfl_up_sync(0xffffffffu, M1, 1);
            float zR = __shfl_up_sync(0xffffffffu, R1, 1);
            float d   = zM - M0;
            float x   = ex2(0.0f - fabsf(d));
            float Mb  = fmaxf(M0, zM);
            float Rhi = (d > 0.0f) ? zR : R0;
            float Rlo = (d > 0.0f) ? R0 : zR;
            float nM0 = Mb + eb[j];
            float nR0 = fmaf(Rlo, x, Rhi);
            float Mq  = allow ? zM : NEG2;
            float m1  = fmaxf(fmaxf(M1, M0), Mq);
            float nR1 = fmaf(R1, ex2(M1 - m1),
                        fmaf(R0, ex2(M0 - m1), zR * ex2(Mq - m1)));
            float nM1 = m1 + el[j];
            bool u = (t < Tlen);
            M0 = (u && in0) ? nM0 : M0;  R0 = (u && in0) ? nR0 : R0;
            M1 = (u && in1) ? nM1 : M1;  R1 = (u && in1) ? nR1 : R1;
        }
        renorm(M0, R0); renorm(M1, R1);
    }

    // ---- fused cost ----
    if (useful) {
        float f0 = in0 ? (M0 + lg2(R0)) : NEG2;
        float f1 = in1 ? (M1 + lg2(R1)) : NEG2;
        shF[p] = make_float2(f0, f1);
    }
    __syncthreads();
    if (tid == 0) {
        int e = label_lens[b]; if (e > P - 1) e = P - 1;
        float a0 = shF[e].x;
        float a1 = (e >= 1) ? shF[e - 1].y : NEG2;
        float m = fmaxf(a0, a1);
        float cost = -(m + lg2(ex2(a0 - m) + ex2(a1 - m))) * 0.69314718055994530942f;
        atomicAdd(out, cost);
    }
}

// ---------------------------------------------------------------------------
extern "C" void kernel_launch(void* const* d_in, const int* in_sizes, int n_in,
                              void* d_out, int out_size)
{
    const float* acts      = (const float*)d_in[0];
    const int*   labels    = (const int*)d_in[1];
    const int*   act_lens  = (const int*)d_in[2];
    const int*   label_len = (const int*)d_in[3];

    int B = in_sizes[2];
    int L = in_sizes[1] / B;
    int V = CTC_V;
    int T = in_sizes[0] / (B * V);

    cudaMemsetAsync(d_out, 0, sizeof(float));

    int rows = T * B;
    int nwarp = (rows + 1) / 2;
    lse_k<<<(nwarp + 7) / 8, 256>>>(acts, rows, T, B);

    ctc_alpha_k<<<B, NTHR>>>((float*)d_out, acts, labels, act_lens, label_len,
                             T, B, L);
}

// round 14
// speedup vs baseline: 1.1873x; 1.1873x over previous
#include <cuda_runtime.h>
#include <cstdint>

#define CTC_V  128
#define NEG2   (-1.0e30f)
#define KS     8                 // time steps per block (== halo depth)
#define UW     (32 - KS)         // useful lanes per warp (24)
#define NW     11
#define NTHR   (NW * 32)         // 352
#define TMAX   1024
#define BMAX   64
#define TP     (TMAX + KS)       // padded time extent (safe unpredicated prefetch)

// Scratch (padded in t so prefetch never leaves the array).
__device__ float g_probs[TP * BMAX * CTC_V];
__device__ float g_blank[BMAX * TP];

__device__ __forceinline__ float ex2(float x) {
    float y; asm("ex2.approx.ftz.f32 %0, %1;" : "=f"(y) : "f"(x)); return y;
}
__device__ __forceinline__ float lg2(float x) {
    float y; asm("lg2.approx.ftz.f32 %0, %1;" : "=f"(y) : "f"(x)); return y;
}
// Exact renorm: fold R's exponent into M; R -> [1,2). Zero/denorm R safe.
__device__ __forceinline__ void renorm(float& M, float& R) {
    unsigned u = __float_as_uint(R);
    unsigned eb = u >> 23;
    int e = (eb != 0u) ? (int)eb - 127 : 0;
    R = __uint_as_float(u - ((unsigned)e << 23));
    M += (float)e;
}

// ---------------------------------------------------------------------------
// Kernel 1: log2-softmax, 2 rows per warp (interleaved for MLP/ILP).
// ---------------------------------------------------------------------------
__global__ void softmax_k(const float* __restrict__ acts, int rows, int T, int B) {
    int gw   = (blockIdx.x * blockDim.x + threadIdx.x) >> 5;
    int lane = threadIdx.x & 31;
    int r0 = gw * 2;
    if (r0 >= rows) return;
    int r1 = r0 + 1;                       // rows = T*B is even
    const float L2E = 1.4426950408889634f;
    float4 va = reinterpret_cast<const float4*>(acts)[(size_t)r0 * 32 + lane];
    float4 vb = reinterpret_cast<const float4*>(acts)[(size_t)r1 * 32 + lane];
    float a0 = va.x * L2E, a1 = va.y * L2E, a2 = va.z * L2E, a3 = va.w * L2E;
    float b0 = vb.x * L2E, b1 = vb.y * L2E, b2 = vb.z * L2E, b3 = vb.w * L2E;
    float ma = fmaxf(fmaxf(a0, a1), fmaxf(a2, a3));
    float mb = fmaxf(fmaxf(b0, b1), fmaxf(b2, b3));
#pragma unroll
    for (int o = 16; o; o >>= 1) {
        ma = fmaxf(ma, __shfl_xor_sync(0xffffffffu, ma, o));
        mb = fmaxf(mb, __shfl_xor_sync(0xffffffffu, mb, o));
    }
    float sa = ex2(a0 - ma) + ex2(a1 - ma) + ex2(a2 - ma) + ex2(a3 - ma);
    float sb = ex2(b0 - mb) + ex2(b1 - mb) + ex2(b2 - mb) + ex2(b3 - mb);
#pragma unroll
    for (int o = 16; o; o >>= 1) {
        sa += __shfl_xor_sync(0xffffffffu, sa, o);
        sb += __shfl_xor_sync(0xffffffffu, sb, o);
    }
    float la = lg2(sa) + ma, lb = lg2(sb) + mb;
    reinterpret_cast<float4*>(g_probs)[(size_t)r0 * 32 + lane] =
        make_float4(a0 - la, a1 - la, a2 - la, a3 - la);
    reinterpret_cast<float4*>(g_probs)[(size_t)r1 * 32 + lane] =
        make_float4(b0 - lb, b1 - lb, b2 - lb, b3 - lb);
    if (lane == 0) {
        int t0 = r0 / B, bb0 = r0 - t0 * B;
        int t1 = r1 / B, bb1 = r1 - t1 * B;
        g_blank[bb0 * TP + t0] = a0 - la;
        g_blank[bb1 * TP + t1] = b0 - lb;
    }
}

// ---------------------------------------------------------------------------
// Kernel 2: alpha recursion, streaming (M,R) logsumexp, common-max step.
// REGISTER-RESIDENT state: useful lanes never touch shared between blocks;
// only halo lanes (lane<KS) reload and only boundary lanes (lane>=UW) store.
// One __syncthreads per block. Unpredicated full blocks + prefetch (padded
// arrays). Renorm once per block. Fused final cost via atomicAdd.
// ---------------------------------------------------------------------------
__global__ __launch_bounds__(NTHR, 1) void ctc_alpha_k(
    float* __restrict__ out,
    const int* __restrict__ labels, const int* __restrict__ act_lens,
    const int* __restrict__ label_lens, int T, int B, int L)
{
    __shared__ __align__(16) float4 shA[2][NW * UW];
    __shared__ float2 shF[NW * UW];

    const int V = CTC_V;
    const int b = blockIdx.x;
    const int P = L + 1;
    const int tid = threadIdx.x, lane = tid & 31, w = tid >> 5;

    int Tlen = act_lens[b];
    if (Tlen > T) Tlen = T;
    if (Tlen < 1) Tlen = 1;

    const int p = w * UW + lane - KS;
    const bool in0 = ((unsigned)p < (unsigned)P);
    const bool in1 = ((unsigned)p < (unsigned)L);
    const int  lab   = in1 ? labels[b * L + p] : 0;
    const bool allow = in1 && (p >= 1) && (lab != labels[b * L + p - 1]);
    const bool useful = (lane >= KS) && in0;

    const float* __restrict__ pl = g_probs + (size_t)b * V + lab;
    const float* __restrict__ pb = g_blank + (size_t)b * TP;
    const size_t rstr = (size_t)B * V;

    // ---- t = 0 init: purely local (every lane computes its own pair) ----
    float M0 = NEG2, R0 = 1.0f, M1 = NEG2, R1 = 1.0f;
    if (p == 0) {
        M0 = __ldg(pb);
        if (in1) M1 = __ldg(pl);
    }

    // emits for block 0 (t = 1..KS) — unpredicated (padded arrays)
    float eb[KS], el[KS];
#pragma unroll
    for (int j = 0; j < KS; ++j) {
        int t = 1 + j;
        eb[j] = __ldg(pb + t);
        el[j] = __ldg(pl + (size_t)t * rstr);
    }

    const int NB     = (Tlen - 1 + KS - 1) / KS;
    const int NBfull = NB > 0 ? NB - 1 : 0;

    for (int blk = 0; blk < NBfull; ++blk) {
        // halo lanes refresh from left neighbor's boundary (written last block)
        if (blk > 0 && lane < KS) {
            float4 v = (p >= 0) ? shA[blk & 1][p] : make_float4(NEG2, 1.f, NEG2, 1.f);
            M0 = v.x; R0 = v.y; M1 = v.z; R1 = v.w;
        }
        // prefetch next block's emits — unpredicated
        float nb_[KS], nl_[KS];
        {
            int tb = (blk + 1) * KS + 1;
#pragma unroll
            for (int j = 0; j < KS; ++j) {
                int t = tb + j;
                nb_[j] = __ldg(pb + t);
                nl_[j] = __ldg(pl + (size_t)t * rstr);
            }
        }

        // 8 common-max steps, unpredicated
#pragma unroll
        for (int j = 0; j < KS; ++j) {
            float zM = __shfl_up_sync(0xffffffffu, M1, 1);
            float zR = __shfl_up_sync(0xffffffffu, R1, 1);
            float mC = fmaxf(fmaxf(M0, M1), zM);
            float x0 = ex2(M0 - mC);
            float x1 = ex2(M1 - mC);
            float xz = ex2(zM - mC);
            float R0x0 = R0 * x0;
            float Rzxz = zR * xz;
            float Rzg  = allow ? Rzxz : 0.0f;
            R0 = R0x0 + Rzxz;
            R1 = fmaf(R1, x1, R0x0 + Rzg);
            M0 = mC + eb[j];
            M1 = mC + el[j];
        }
        renorm(M0, R0); renorm(M1, R1);

        // only boundary lanes publish for the right neighbor's halo
        if (lane >= UW) shA[(blk + 1) & 1][p] = make_float4(M0, R0, M1, R1);
        __syncthreads();

#pragma unroll
        for (int j = 0; j < KS; ++j) { eb[j] = nb_[j]; el[j] = nl_[j]; }
    }

    // ---- tail block (predicated, per-state max) ----
    if (NB > 0) {
        int blk = NBfull;
        if (blk > 0 && lane < KS) {
            float4 v = (p >= 0) ? shA[blk & 1][p] : make_float4(NEG2, 1.f, NEG2, 1.f);
            M0 = v.x; R0 = v.y; M1 = v.z; R1 = v.w;
        }
#pragma unroll
        for (int j = 0; j < KS; ++j) {
            int t = blk * KS + 1 + j;
            float zM = __shfl_up_sync(0xffffffffu, M1, 1);
            float zR = __shfl_up_sync(0xffffffffu, R1, 1);
            float d   = zM - M0;
            float x   = ex2(0.0f - fabsf(d));
            float Mb  = fmaxf(M0, zM);
            float Rhi = (d > 0.0f) ? zR : R0;
            float Rlo = (d > 0.0f) ? R0 : zR;
            float nM0 = Mb + eb[j];
            float nR0 = fmaf(Rlo, x, Rhi);
            float Mq  = allow ? zM : NEG2;
            float m1  = fmaxf(fmaxf(M1, M0), Mq);
            float nR1 = fmaf(R1, ex2(M1 - m1),
                        fmaf(R0, ex2(M0 - m1), zR * ex2(Mq - m1)));
            float nM1 = m1 + el[j];
            bool u = (t < Tlen);
            M0 = (u && in0) ? nM0 : M0;  R0 = (u && in0) ? nR0 : R0;
            M1 = (u && in1) ? nM1 : M1;  R1 = (u && in1) ? nR1 : R1;
        }
        renorm(M0, R0); renorm(M1, R1);
    }

    // ---- fused cost ----
    if (useful) {
        float f0 = in0 ? (M0 + lg2(R0)) : NEG2;
        float f1 = in1 ? (M1 + lg2(R1)) : NEG2;
        shF[p] = make_float2(f0, f1);
    }
    __syncthreads();
    if (tid == 0) {
        int e = label_lens[b]; if (e > P - 1) e = P - 1;
        float a0 = shF[e].x;
        float a1 = (e >= 1) ? shF[e - 1].y : NEG2;
        float m = fmaxf(a0, a1);
        float cost = -(m + lg2(ex2(a0 - m) + ex2(a1 - m))) * 0.69314718055994530942f;
        atomicAdd(out, cost);
    }
}

// ---------------------------------------------------------------------------
extern "C" void kernel_launch(void* const* d_in, const int* in_sizes, int n_in,
                              void* d_out, int out_size)
{
    const float* acts      = (const float*)d_in[0];
    const int*   labels    = (const int*)d_in[1];
    const int*   act_lens  = (const int*)d_in[2];
    const int*   label_len = (const int*)d_in[3];

    int B = in_sizes[2];
    int L = in_sizes[1] / B;
    int V = CTC_V;
    int T = in_sizes[0] / (B * V);

    cudaMemsetAsync(d_out, 0, sizeof(float));

    int rows = T * B;
    int nwarp = (rows + 1) / 2;
    softmax_k<<<(nwarp + 7) / 8, 256>>>(acts, rows, T, B);

    ctc_alpha_k<<<B, NTHR>>>((float*)d_out, labels, act_lens, label_len, T, B, L);
}